// round 16
// baseline (speedup 1.0000x reference)
#include <cuda_runtime.h>
#include <cuda_fp16.h>
#include <math.h>
#include <stdint.h>

// Problem constants (fixed shapes)
#define BATCH 2
#define SEQ   2048
#define DM    1024
#define NH    16
#define DH    64
#define MROWS (BATCH*SEQ)          // 4096
#define QKV_OFF (BATCH*NH*SEQ*DH)  // 4194304

// Scratch (device globals; allocation-free)
__device__ __half g_X16[MROWS*DM];      // x in fp16, [M, K]
__device__ __half g_QKV[3*QKV_OFF];     // Q | K | V in [B,H,S,dh], fp16
__device__ __half g_ATT[MROWS*DM];      // attention output, fp16
__device__ __half g_WQKV[DM*3*DM];      // [K=1024, N=3072]: Wq*s | Wk | Wv
__device__ __half g_WO[DM*DM];          // Wo [K, N] fp16
__device__ float  g_BIAS[3*DM];         // packed bq*s | bk | bv (fp32)

#define LOG2E 1.4426950408889634f

// ===========================================================================
// Helpers (baseline sm_80 PTX only)
// ===========================================================================
__device__ __forceinline__ void cp16(uint32_t s, const void* g) {
    asm volatile("cp.async.cg.shared.global [%0], [%1], 16;" :: "r"(s), "l"(g));
}
#define CP_COMMIT() asm volatile("cp.async.commit_group;" ::: "memory")
#define CP_WAIT(N)  asm volatile("cp.async.wait_group %0;" :: "n"(N) : "memory")

__device__ __forceinline__ void ldm_x4(uint32_t r[4], uint32_t a) {
    asm volatile("ldmatrix.sync.aligned.m8n8.x4.shared.b16 {%0,%1,%2,%3}, [%4];"
                 : "=r"(r[0]), "=r"(r[1]), "=r"(r[2]), "=r"(r[3]) : "r"(a));
}
__device__ __forceinline__ void ldm_x4t(uint32_t r[4], uint32_t a) {
    asm volatile("ldmatrix.sync.aligned.m8n8.x4.trans.shared.b16 {%0,%1,%2,%3}, [%4];"
                 : "=r"(r[0]), "=r"(r[1]), "=r"(r[2]), "=r"(r[3]) : "r"(a));
}

// f32-accumulate MMA (rt16 — the measured sm_103a mma.sync ceiling)
__device__ __forceinline__ void mma_f16(float c[4],
    uint32_t a0, uint32_t a1, uint32_t a2, uint32_t a3,
    uint32_t b0, uint32_t b1)
{
    asm volatile(
        "mma.sync.aligned.m16n8k16.row.col.f32.f16.f16.f32 "
        "{%0,%1,%2,%3}, {%4,%5,%6,%7}, {%8,%9}, {%0,%1,%2,%3};"
        : "+f"(c[0]), "+f"(c[1]), "+f"(c[2]), "+f"(c[3])
        : "r"(a0), "r"(a1), "r"(a2), "r"(a3), "r"(b0), "r"(b1));
}

__device__ __forceinline__ uint32_t pack2(float a, float b) {
    __half2 h = __floats2half2_rn(a, b);
    return *(uint32_t*)&h;
}
__device__ __forceinline__ uint32_t ex2_h2(uint32_t x) {
    uint32_t r;
    asm("ex2.approx.f16x2 %0, %1;" : "=r"(r) : "r"(x));
    return r;
}

// ===========================================================================
// Fused prep (pure streaming, coalesced) — champion version, unchanged
// ===========================================================================
__global__ void __launch_bounds__(256) prep(
    const float* __restrict__ x,
    const float* __restrict__ Wq, const float* __restrict__ Wk,
    const float* __restrict__ Wv, const float* __restrict__ Wo,
    const float* __restrict__ bq, const float* __restrict__ bk,
    const float* __restrict__ bv,
    __half* __restrict__ x16, __half* __restrict__ wqkv,
    __half* __restrict__ wo16, float* __restrict__ bias)
{
    const int blk = blockIdx.x;
    const int tid = threadIdx.x;
    const float qs = 0.125f * LOG2E;   // 1/sqrt(dh) * log2(e), folded into Wq/bq

    if (blk < 1024) {
#pragma unroll
        for (int p = 0; p < 4; p++) {
            const int j = blk * 1024 + p * 256 + tid;
            float4 v = *(const float4*)(x + (size_t)j * 4);
            *(__half2*)(x16 + (size_t)j * 4)     = __floats2half2_rn(v.x, v.y);
            *(__half2*)(x16 + (size_t)j * 4 + 2) = __floats2half2_rn(v.z, v.w);
        }
        return;
    }
    if (blk < 1792) {
        const int i = blk - 1024;
        const int which = i >> 8;
        const int bi = i & 255;
        const float* W = (which == 0) ? Wq : (which == 1) ? Wk : Wv;
        const float scale = (which == 0) ? qs : 1.0f;
#pragma unroll
        for (int p = 0; p < 4; p++) {
            const int e = bi * 4096 + (p * 256 + tid) * 4;
            const int k = e >> 10, n = e & 1023;
            float4 v = *(const float4*)(W + e);
            __half* dst = wqkv + (size_t)k * 3072 + which * 1024 + n;
            *(__half2*)(dst)     = __floats2half2_rn(v.x * scale, v.y * scale);
            *(__half2*)(dst + 2) = __floats2half2_rn(v.z * scale, v.w * scale);
        }
        return;
    }
    if (blk < 2048) {
        const int bi = blk - 1792;
#pragma unroll
        for (int p = 0; p < 4; p++) {
            const int e = bi * 4096 + (p * 256 + tid) * 4;
            float4 v = *(const float4*)(Wo + e);
            *(__half2*)(wo16 + e)     = __floats2half2_rn(v.x, v.y);
            *(__half2*)(wo16 + e + 2) = __floats2half2_rn(v.z, v.w);
        }
        return;
    }
#pragma unroll
    for (int j = 0; j < 12; j++) {
        const int i = j * 256 + tid;
        float v;
        if (i < 1024)       v = bq[i] * qs;
        else if (i < 2048)  v = bk[i - 1024];
        else                v = bv[i - 2048];
        bias[i] = v;
    }
}

// ===========================================================================
// Shared tile-loader geometry
// ===========================================================================
#define ROWB   144                      // A rows: 64 halfs + 16B pad
#define ROWB_B 272                      // B rows: 128 halfs + 16B pad

// ===========================================================================
// GEMM variant 1 (champion, O-proj): 512 thr, block 256x128, 16 warps
// (8m x 2n), warp tile 32x64, BK=64, 3-stage cp.async, 1 CTA/SM.
// ===========================================================================
#define GA_TILEB (256 * ROWB)           // 36864
#define GB_TILEB (64 * ROWB_B)          // 17408
#define G_STAGE  (GA_TILEB + GB_TILEB)  // 54272
#define G_SMEM   (3 * G_STAGE)          // 162816

__device__ __forceinline__ void g_load_A(
    const __half* __restrict__ G, uint32_t sbase, int tid)
{
#pragma unroll
    for (int i = 0; i < 4; i++) {
        const int idx = tid + (i << 9);
        const int r = idx >> 3, s = idx & 7;
        cp16(sbase + (uint32_t)(r * ROWB + s * 16), G + (size_t)r * DM + s * 8);
    }
}
__device__ __forceinline__ void g_load_Bw(
    const __half* __restrict__ G, int wstride, uint32_t sbase, int tid)
{
#pragma unroll
    for (int i = 0; i < 2; i++) {
        const int idx = tid + (i << 9);
        const int r = idx >> 4, s = idx & 15;
        cp16(sbase + (uint32_t)(r * ROWB_B + s * 16), G + (size_t)r * wstride + s * 8);
    }
}

__global__ void __launch_bounds__(512, 1) gemm_f16(
    const __half* __restrict__ A, const __half* __restrict__ W, int wstride,
    const float* __restrict__ bias, void* __restrict__ Cout, int mode)
{
    extern __shared__ __align__(16) char smraw[];
    const uint32_t smem0 = (uint32_t)__cvta_generic_to_shared(smraw);

    const int tid  = threadIdx.x;
    const int wid  = tid >> 5, lane = tid & 31;
    const int wm   = wid >> 1, wn = wid & 1;
    const int g    = lane >> 2, kq = lane & 3;
    const int lrow = lane & 15;
    const int lcol = (lane >> 4) * 16;

    const int m0 = blockIdx.y * 256;
    const int n0 = blockIdx.x * 128;

    const __half* Ag = A + (size_t)m0 * DM;
    const __half* Wg = W + n0;

    float c[2][8][4];
#pragma unroll
    for (int mt = 0; mt < 2; mt++)
#pragma unroll
        for (int nt = 0; nt < 8; nt++)
#pragma unroll
            for (int i = 0; i < 4; i++) c[mt][nt][i] = 0.f;

    g_load_A(Ag, smem0, tid);
    g_load_Bw(Wg, wstride, smem0 + GA_TILEB, tid);
    CP_COMMIT();
    g_load_A(Ag + 64, smem0 + G_STAGE, tid);
    g_load_Bw(Wg + (size_t)64 * wstride, wstride, smem0 + G_STAGE + GA_TILEB, tid);
    CP_COMMIT();

    const int NCH = DM / 64;            // 16
    for (int kc = 0; kc < NCH; kc++) {
        if (kc < NCH - 1) { CP_WAIT(1); } else { CP_WAIT(0); }
        __syncthreads();

        if (kc + 2 < NCH) {
            const uint32_t sb = smem0 + (uint32_t)(((kc + 2) % 3) * G_STAGE);
            g_load_A(Ag + (kc + 2) * 64, sb, tid);
            g_load_Bw(Wg + (size_t)(kc + 2) * 64 * wstride, wstride, sb + GA_TILEB, tid);
            CP_COMMIT();
        }

        const uint32_t sA = smem0 + (uint32_t)((kc % 3) * G_STAGE);
        const uint32_t sB = sA + GA_TILEB;
        const uint32_t aBase = sA + (uint32_t)((wm * 32 + lrow) * ROWB) + lcol;
        const uint32_t bBase = sB + (uint32_t)(lrow * ROWB_B) + (uint32_t)(wn * 128) + lcol;

#pragma unroll
        for (int ks = 0; ks < 4; ks++) {
            uint32_t af[2][4], bf[4][4];
#pragma unroll
            for (int mt = 0; mt < 2; mt++)
                ldm_x4(af[mt], aBase + (uint32_t)(mt * 16 * ROWB) + ks * 32);
#pragma unroll
            for (int np = 0; np < 4; np++)
                ldm_x4t(bf[np], bBase + (uint32_t)(ks * 16 * ROWB_B) + np * 32);
#pragma unroll
            for (int mt = 0; mt < 2; mt++) {
#pragma unroll
                for (int np = 0; np < 4; np++) {
                    mma_f16(c[mt][2*np],   af[mt][0], af[mt][1], af[mt][2], af[mt][3],
                            bf[np][0], bf[np][1]);
                    mma_f16(c[mt][2*np+1], af[mt][0], af[mt][1], af[mt][2], af[mt][3],
                            bf[np][2], bf[np][3]);
                }
            }
        }
    }

#pragma unroll
    for (int mt = 0; mt < 2; mt++) {
        const int r1 = m0 + wm * 32 + mt * 16 + g;
        const int r2 = r1 + 8;
        const int b1 = r1 >> 11, s1 = r1 & 2047;
        const int b2 = r2 >> 11, s2 = r2 & 2047;
#pragma unroll
        for (int nt = 0; nt < 8; nt++) {
            const int n = n0 + wn * 64 + nt * 8 + 2 * kq;
            const float bx = bias[n], by = bias[n + 1];
            const float v10 = c[mt][nt][0] + bx, v11 = c[mt][nt][1] + by;
            const float v20 = c[mt][nt][2] + bx, v21 = c[mt][nt][3] + by;
            if (mode == 0) {
                __half* C = (__half*)Cout;
                const int which = n >> 10;
                const int nn = n & 1023;
                const int h = nn >> 6, d = nn & 63;
                const size_t base = (size_t)which * QKV_OFF;
                *(__half2*)(C + base + (((size_t)(b1 * NH + h)) * SEQ + s1) * DH + d) =
                    __floats2half2_rn(v10, v11);
                *(__half2*)(C + base + (((size_t)(b2 * NH + h)) * SEQ + s2) * DH + d) =
                    __floats2half2_rn(v20, v21);
            } else {
                float* C = (float*)Cout;
                *(float2*)(C + (size_t)r1 * DM + n) = make_float2(v10, v11);
                *(float2*)(C + (size_t)r2 * DM + n) = make_float2(v20, v21);
            }
        }
    }
}

// ===========================================================================
// GEMM variant 2 (QKV): block 128x128, 256 thr, 8 warps (4m x 2n),
// SAME 32x64 warp tile & inner loop as champion. 3-stage cp.async,
// smem 105 KB... = 3 * (18432 + 17408) = 107520 -> 2 CTAs/SM (RF-exact).
// Fine CTA granularity removes the QKV wave tail.
// ===========================================================================
#define H_ATILEB (128 * ROWB)           // 18432
#define H_STAGE  (H_ATILEB + GB_TILEB)  // 35840
#define H_SMEM   (3 * H_STAGE)          // 107520

__device__ __forceinline__ void h_load_A(
    const __half* __restrict__ G, uint32_t sbase, int tid)
{
#pragma unroll
    for (int i = 0; i < 4; i++) {       // 128 rows x 8 segs / 256 thr
        const int idx = tid + (i << 8);
        const int r = idx >> 3, s = idx & 7;
        cp16(sbase + (uint32_t)(r * ROWB + s * 16), G + (size_t)r * DM + s * 8);
    }
}
__device__ __forceinline__ void h_load_Bw(
    const __half* __restrict__ G, int wstride, uint32_t sbase, int tid)
{
#pragma unroll
    for (int i = 0; i < 4; i++) {       // 64 rows x 16 segs / 256 thr
        const int idx = tid + (i << 8);
        const int r = idx >> 4, s = idx & 15;
        cp16(sbase + (uint32_t)(r * ROWB_B + s * 16), G + (size_t)r * wstride + s * 8);
    }
}

__global__ void __launch_bounds__(256, 2) gemm_f16_h(
    const __half* __restrict__ A, const __half* __restrict__ W, int wstride,
    const float* __restrict__ bias, __half* __restrict__ Cout)
{
    extern __shared__ __align__(16) char smraw[];
    const uint32_t smem0 = (uint32_t)__cvta_generic_to_shared(smraw);

    const int tid  = threadIdx.x;
    const int wid  = tid >> 5, lane = tid & 31;
    const int wm   = wid >> 1, wn = wid & 1;   // 4m x 2n
    const int g    = lane >> 2, kq = lane & 3;
    const int lrow = lane & 15;
    const int lcol = (lane >> 4) * 16;

    const int m0 = blockIdx.y * 128;
    const int n0 = blockIdx.x * 128;

    const __half* Ag = A + (size_t)m0 * DM;
    const __half* Wg = W + n0;

    float c[2][8][4];
#pragma unroll
    for (int mt = 0; mt < 2; mt++)
#pragma unroll
        for (int nt = 0; nt < 8; nt++)
#pragma unroll
            for (int i = 0; i < 4; i++) c[mt][nt][i] = 0.f;

    h_load_A(Ag, smem0, tid);
    h_load_Bw(Wg, wstride, smem0 + H_ATILEB, tid);
    CP_COMMIT();
    h_load_A(Ag + 64, smem0 + H_STAGE, tid);
    h_load_Bw(Wg + (size_t)64 * wstride, wstride, smem0 + H_STAGE + H_ATILEB, tid);
    CP_COMMIT();

    const int NCH = DM / 64;            // 16
    for (int kc = 0; kc < NCH; kc++) {
        if (kc < NCH - 1) { CP_WAIT(1); } else { CP_WAIT(0); }
        __syncthreads();

        if (kc + 2 < NCH) {
            const uint32_t sb = smem0 + (uint32_t)(((kc + 2) % 3) * H_STAGE);
            h_load_A(Ag + (kc + 2) * 64, sb, tid);
            h_load_Bw(Wg + (size_t)(kc + 2) * 64 * wstride, wstride, sb + H_ATILEB, tid);
            CP_COMMIT();
        }

        const uint32_t sA = smem0 + (uint32_t)((kc % 3) * H_STAGE);
        const uint32_t sB = sA + H_ATILEB;
        const uint32_t aBase = sA + (uint32_t)((wm * 32 + lrow) * ROWB) + lcol;
        const uint32_t bBase = sB + (uint32_t)(lrow * ROWB_B) + (uint32_t)(wn * 128) + lcol;

#pragma unroll
        for (int ks = 0; ks < 4; ks++) {
            uint32_t af[2][4], bf[4][4];
#pragma unroll
            for (int mt = 0; mt < 2; mt++)
                ldm_x4(af[mt], aBase + (uint32_t)(mt * 16 * ROWB) + ks * 32);
#pragma unroll
            for (int np = 0; np < 4; np++)
                ldm_x4t(bf[np], bBase + (uint32_t)(ks * 16 * ROWB_B) + np * 32);
#pragma unroll
            for (int mt = 0; mt < 2; mt++) {
#pragma unroll
                for (int np = 0; np < 4; np++) {
                    mma_f16(c[mt][2*np],   af[mt][0], af[mt][1], af[mt][2], af[mt][3],
                            bf[np][0], bf[np][1]);
                    mma_f16(c[mt][2*np+1], af[mt][0], af[mt][1], af[mt][2], af[mt][3],
                            bf[np][2], bf[np][3]);
                }
            }
        }
    }

    // Epilogue (QKV remap only)
#pragma unroll
    for (int mt = 0; mt < 2; mt++) {
        const int r1 = m0 + wm * 32 + mt * 16 + g;
        const int r2 = r1 + 8;
        const int b1 = r1 >> 11, s1 = r1 & 2047;
        const int b2 = r2 >> 11, s2 = r2 & 2047;
#pragma unroll
        for (int nt = 0; nt < 8; nt++) {
            const int n = n0 + wn * 64 + nt * 8 + 2 * kq;
            const float bx = bias[n], by = bias[n + 1];
            const float v10 = c[mt][nt][0] + bx, v11 = c[mt][nt][1] + by;
            const float v20 = c[mt][nt][2] + bx, v21 = c[mt][nt][3] + by;
            const int which = n >> 10;
            const int nn = n & 1023;
            const int h = nn >> 6, d = nn & 63;
            const size_t base = (size_t)which * QKV_OFF;
            *(__half2*)(Cout + base + (((size_t)(b1 * NH + h)) * SEQ + s1) * DH + d) =
                __floats2half2_rn(v10, v11);
            *(__half2*)(Cout + base + (((size_t)(b2 * NH + h)) * SEQ + s2) * DH + d) =
                __floats2half2_rn(v20, v21);
        }
    }
}

// ===========================================================================
// Flash attention (R15 champion): q-tile 256, 8 warps/block, m32/warp,
// BK=128, f32-acc mma, log2-domain scores, P = ex2.approx.f16x2,
// row sums via hadd2 tree on fma/alu pipes.
// ===========================================================================
#define FAQ_BYTES  (256 * ROWB)          // 36864
#define FAKV_BYTES (128 * ROWB)          // 18432
#define FA_SMEM (FAQ_BYTES + 4 * FAKV_BYTES)   // 110592

__device__ __forceinline__ void fa_load_q(
    const __half* __restrict__ G, uint32_t sbase, int tid)
{
#pragma unroll
    for (int i = 0; i < 8; i++) {
        const int idx = tid + (i << 8);
        const int r = idx >> 3, s = idx & 7;
        cp16(sbase + (uint32_t)(r * ROWB + s * 16), G + (size_t)r * DH + s * 8);
    }
}
__device__ __forceinline__ void fa_load_kv(
    const __half* __restrict__ G, uint32_t sbase, int tid)
{
#pragma unroll
    for (int i = 0; i < 4; i++) {
        const int idx = tid + (i << 8);
        const int r = idx >> 3, s = idx & 7;
        cp16(sbase + (uint32_t)(r * ROWB + s * 16), G + (size_t)r * DH + s * 8);
    }
}

__global__ void __launch_bounds__(256) fa_mma(
    const __half* __restrict__ Q, const __half* __restrict__ K,
    const __half* __restrict__ V, __half* __restrict__ Out)
{
    extern __shared__ __align__(16) char smraw[];
    const uint32_t smem0 = (uint32_t)__cvta_generic_to_shared(smraw);
    const uint32_t smQ  = smem0;
    const uint32_t smK0 = smem0 + FAQ_BYTES;
    const uint32_t smK1 = smK0 + FAKV_BYTES;
    const uint32_t smV0 = smK1 + FAKV_BYTES;
    const uint32_t smV1 = smV0 + FAKV_BYTES;

    const int tid = threadIdx.x;
    const int wid = tid >> 5, lane = tid & 31;
    const int g = lane >> 2, kq = lane & 3;
    const int lrow = lane & 15;
    const int lcol = (lane >> 4) * 16;

    const int q0 = blockIdx.x * 256;
    const int bh = blockIdx.y;
    const int b = bh >> 4, h = bh & 15;

    const __half* Qg = Q + (size_t)bh * SEQ * DH + (size_t)q0 * DH;
    const __half* Kg = K + (size_t)bh * SEQ * DH;
    const __half* Vg = V + (size_t)bh * SEQ * DH;

    fa_load_q(Qg, smQ, tid);
    CP_COMMIT();
    fa_load_kv(Kg, smK0, tid);
    fa_load_kv(Vg, smV0, tid);
    CP_COMMIT();

    float mx[2][2], li[2][2];
    float co[2][8][4];
#pragma unroll
    for (int mh = 0; mh < 2; mh++) {
        mx[mh][0] = mx[mh][1] = -INFINITY;
        li[mh][0] = li[mh][1] = 0.f;
#pragma unroll
        for (int nt = 0; nt < 8; nt++)
#pragma unroll
            for (int i = 0; i < 4; i++) co[mh][nt][i] = 0.f;
    }

    const uint32_t qBase = smQ + (uint32_t)((wid * 32 + lrow) * ROWB) + lcol;

    for (int t = 0; t < SEQ / 128; t++) {
        __syncthreads();
        if (t + 1 < SEQ / 128) {
            const uint32_t sKn = ((t + 1) & 1) ? smK1 : smK0;
            const uint32_t sVn = ((t + 1) & 1) ? smV1 : smV0;
            fa_load_kv(Kg + (size_t)(t + 1) * 128 * DH, sKn, tid);
            fa_load_kv(Vg + (size_t)(t + 1) * 128 * DH, sVn, tid);
            CP_COMMIT();
            CP_WAIT(1);
        } else {
            CP_WAIT(0);
        }
        __syncthreads();

        const uint32_t sK = (t & 1) ? smK1 : smK0;
        const uint32_t sV = (t & 1) ? smV1 : smV0;
        const uint32_t kBase = sK + (uint32_t)(lrow * ROWB) + lcol;
        const uint32_t vBase = sV + (uint32_t)(lrow * ROWB) + lcol;

        // ---- scores (log2 domain), f32 acc: S[32 x 128] per warp ----
        float cs[2][16][4];
#pragma unroll
        for (int mh = 0; mh < 2; mh++)
#pragma unroll
            for (int nt = 0; nt < 16; nt++)
#pragma unroll
                for (int i = 0; i < 4; i++) cs[mh][nt][i] = 0.f;

#pragma unroll
        for (int ks = 0; ks < 4; ks++) {
            uint32_t a[2][4];
            ldm_x4(a[0], qBase + ks * 32);
            ldm_x4(a[1], qBase + (uint32_t)(16 * ROWB) + ks * 32);
#pragma unroll
            for (int np = 0; np < 8; np++) {
                uint32_t bb[4];
                ldm_x4(bb, kBase + (uint32_t)(np * 16 * ROWB) + ks * 32);
#pragma unroll
                for (int mh = 0; mh < 2; mh++) {
                    mma_f16(cs[mh][2*np],   a[mh][0], a[mh][1], a[mh][2], a[mh][3],
                            bb[0], bb[2]);
                    mma_f16(cs[mh][2*np+1], a[mh][0], a[mh][1], a[mh][2], a[mh][3],
                            bb[1], bb[3]);
                }
            }
        }

        // ---- online softmax: f32 max + P = 2^(s-m) via ex2.approx.f16x2 ----
        uint32_t p[2][16][2];
        float corr[2][2];
#pragma unroll
        for (int mh = 0; mh < 2; mh++) {
            float tm0 = -INFINITY, tm1 = -INFINITY;
#pragma unroll
            for (int nt = 0; nt < 16; nt++) {
                tm0 = fmaxf(tm0, fmaxf(cs[mh][nt][0], cs[mh][nt][1]));
                tm1 = fmaxf(tm1, fmaxf(cs[mh][nt][2], cs[mh][nt][3]));
            }
            tm0 = fmaxf(tm0, __shfl_xor_sync(0xffffffffu, tm0, 1));
            tm0 = fmaxf(tm0, __shfl_xor_sync(0xffffffffu, tm0, 2));
            tm1 = fmaxf(tm1, __shfl_xor_sync(0xffffffffu, tm1, 1));
            tm1 = fmaxf(tm1, __shfl_xor_sync(0xffffffffu, tm1, 2));

            const float mn0 = fmaxf(mx[mh][0], tm0), mn1 = fmaxf(mx[mh][1], tm1);
            corr[mh][0] = exp2f(mx[mh][0] - mn0);
            corr[mh][1] = exp2f(mx[mh][1] - mn1);
            mx[mh][0] = mn0; mx[mh][1] = mn1;

#pragma unroll
            for (int nt = 0; nt < 16; nt++) {
                p[mh][nt][0] = ex2_h2(pack2(cs[mh][nt][0] - mn0, cs[mh][nt][1] - mn0));
                p[mh][nt][1] = ex2_h2(pack2(cs[mh][nt][2] - mn1, cs[mh][nt][3] - mn1));
            }

            float ts[2];
#pragma unroll
            for (int hf = 0; hf < 2; hf++) {
                __half2 l1[8];
#pragma unroll
                for (int i = 0; i < 8; i++)
                    l1[i] = __hadd2(*(__half2*)&p[mh][2*i][hf],
                                    *(__half2*)&p[mh][2*i+1][hf]);
                __half2 l2[4];
#pragma unroll
                for (int i = 0; i < 4; i++)
                    l2[i] = __hadd2(l1[2*i], l1[2*i+1]);
                float s = 0.f;
#pragma unroll
                for (int i = 0; i < 4; i++) {
                    const float2 f = __half22float2(l2[i]);
                    s += f.x + f.y;
                }
                s += __shfl_xor_sync(0xffffffffu, s, 1);
                s += __shfl_xor_sync(0xffffffffu, s, 2);
                ts[hf] = s;
            }
            li[mh][0] = li[mh][0] * corr[mh][0] + ts[0];
            li[mh][1] = li[mh][1] * corr[mh][1] + ts[1];

#pragma unroll
            for (int nt = 0; nt < 8; nt++) {
                co[mh][nt][0] *= corr[mh][0]; co[mh][nt][1] *= corr[mh][0];
                co[mh][nt][2] *= corr[mh][1]; co[mh][nt][3] *= corr[mh][1];
            }
        }

        // ---- PV (f32 acc) ----
#pragma unroll
        for (int j = 0; j < 8; j++) {
            uint32_t bb[4][4];
#pragma unroll
            for (int np = 0; np < 4; np++)
                ldm_x4t(bb[np], vBase + (uint32_t)(j * 16 * ROWB) + np * 32);
#pragma unroll
            for (int mh = 0; mh < 2; mh++) {
                const uint32_t a0 = p[mh][2*j][0];
                const uint32_t a1 = p[mh][2*j][1];
                const uint32_t a2 = p[mh][2*j+1][0];
                const uint32_t a3 = p[mh][2*j+1][1];
#pragma unroll
                for (int np = 0; np < 4; np++) {
                    mma_f16(co[mh][2*np],   a0, a1, a2, a3, bb[np][0], bb[np][1]);
                    mma_f16(co[mh][2*np+1], a0, a1, a2, a3, bb[np][2], bb[np][3]);
                }
            }
        }
    }

    // ---- epilogue: normalize, write fp16 [B, S, H*dh] ----
#pragma unroll
    for (int mh = 0; mh < 2; mh++) {
        const float inv0 = 1.f / li[mh][0], inv1 = 1.f / li[mh][1];
        const int qrow = wid * 32 + mh * 16 + g;
        __half* Og = Out + ((size_t)b * SEQ + (q0 + qrow)) * DM + h * DH;
#pragma unroll
        for (int nt = 0; nt < 8; nt++) {
            *(__half2*)(Og + 8 * nt + 2 * kq) =
                __floats2half2_rn(co[mh][nt][0] * inv0, co[mh][nt][1] * inv0);
            *(__half2*)(Og + (size_t)8 * DM + 8 * nt + 2 * kq) =
                __floats2half2_rn(co[mh][nt][2] * inv1, co[mh][nt][3] * inv1);
        }
    }
}

// ---------------------------------------------------------------------------
// Launch
// ---------------------------------------------------------------------------
extern "C" void kernel_launch(void* const* d_in, const int* in_sizes, int n_in,
                              void* d_out, int out_size)
{
    const float* x  = (const float*)d_in[0];
    // d_in[1] = pH : constant along softmax axis -> provably no effect
    const float* Wq = (const float*)d_in[2];
    const float* bq = (const float*)d_in[3];
    const float* Wk = (const float*)d_in[4];
    const float* bk = (const float*)d_in[5];
    const float* Wv = (const float*)d_in[6];
    const float* bv = (const float*)d_in[7];
    const float* Wo = (const float*)d_in[8];
    const float* bo = (const float*)d_in[9];
    float* out = (float*)d_out;

    __half *x16, *qkv, *att, *wqkv, *wo16;
    float *bias;
    cudaGetSymbolAddress((void**)&x16,  g_X16);
    cudaGetSymbolAddress((void**)&qkv,  g_QKV);
    cudaGetSymbolAddress((void**)&att,  g_ATT);
    cudaGetSymbolAddress((void**)&wqkv, g_WQKV);
    cudaGetSymbolAddress((void**)&wo16, g_WO);
    cudaGetSymbolAddress((void**)&bias, g_BIAS);

    cudaFuncSetAttribute(gemm_f16,   cudaFuncAttributeMaxDynamicSharedMemorySize, G_SMEM);
    cudaFuncSetAttribute(gemm_f16_h, cudaFuncAttributeMaxDynamicSharedMemorySize, H_SMEM);
    cudaFuncSetAttribute(fa_mma,     cudaFuncAttributeMaxDynamicSharedMemorySize, FA_SMEM);

    // Fused streaming prep: f2h(x) + W pack/convert (no transpose) + bias
    prep<<<2049, 256>>>(x, Wq, Wk, Wv, Wo, bq, bk, bv, x16, wqkv, wo16, bias);

    // Merged QKV projection: 128x128 tiles, 2 CTAs/SM (wave-tail-free)
    dim3 gq(3 * DM / 128, MROWS / 128);   // (24, 32) = 768 CTAs
    gemm_f16_h<<<gq, 256, H_SMEM>>>(x16, wqkv, 3072, bias, qkv);

    // Attention, q-tile 256 (champion config)
    dim3 ga(SEQ / 256, BATCH * NH);       // (8, 32) = 256 CTAs
    fa_mma<<<ga, 256, FA_SMEM>>>(qkv, qkv + QKV_OFF, qkv + 2 * QKV_OFF, att);

    // Output projection (fp32 out) — champion kernel, single wave
    dim3 go(DM / 128, MROWS / 256);       // (8, 16)
    gemm_f16<<<go, 512, G_SMEM>>>(att, wo16, 1024, bo, out, 1);
}

// round 17
// speedup vs baseline: 1.0045x; 1.0045x over previous
#include <cuda_runtime.h>
#include <cuda_fp16.h>
#include <math.h>
#include <stdint.h>

// Problem constants (fixed shapes)
#define BATCH 2
#define SEQ   2048
#define DM    1024
#define NH    16
#define DH    64
#define MROWS (BATCH*SEQ)          // 4096
#define QKV_OFF (BATCH*NH*SEQ*DH)  // 4194304

// Scratch (device globals; allocation-free)
__device__ __half g_X16[MROWS*DM];      // x in fp16, [M, K]
__device__ __half g_QKV[3*QKV_OFF];     // Q | K | V in [B,H,S,dh], fp16
__device__ __half g_ATT[MROWS*DM];      // attention output, fp16
__device__ __half g_WQKV[DM*3*DM];      // [K=1024, N=3072]: Wq*s | Wk | Wv
__device__ __half g_WO[DM*DM];          // Wo [K, N] fp16
__device__ float  g_BIAS[3*DM];         // packed bq*s | bk | bv (fp32)

#define LOG2E 1.4426950408889634f

// ===========================================================================
// Helpers (baseline sm_80 PTX only)
// ===========================================================================
__device__ __forceinline__ void cp16(uint32_t s, const void* g) {
    asm volatile("cp.async.cg.shared.global [%0], [%1], 16;" :: "r"(s), "l"(g));
}
#define CP_COMMIT() asm volatile("cp.async.commit_group;" ::: "memory")
#define CP_WAIT(N)  asm volatile("cp.async.wait_group %0;" :: "n"(N) : "memory")

__device__ __forceinline__ void ldm_x4(uint32_t r[4], uint32_t a) {
    asm volatile("ldmatrix.sync.aligned.m8n8.x4.shared.b16 {%0,%1,%2,%3}, [%4];"
                 : "=r"(r[0]), "=r"(r[1]), "=r"(r[2]), "=r"(r[3]) : "r"(a));
}
__device__ __forceinline__ void ldm_x4t(uint32_t r[4], uint32_t a) {
    asm volatile("ldmatrix.sync.aligned.m8n8.x4.trans.shared.b16 {%0,%1,%2,%3}, [%4];"
                 : "=r"(r[0]), "=r"(r[1]), "=r"(r[2]), "=r"(r[3]) : "r"(a));
}

// f32-accumulate MMA (rt16 — the measured sm_103a mma.sync ceiling)
__device__ __forceinline__ void mma_f16(float c[4],
    uint32_t a0, uint32_t a1, uint32_t a2, uint32_t a3,
    uint32_t b0, uint32_t b1)
{
    asm volatile(
        "mma.sync.aligned.m16n8k16.row.col.f32.f16.f16.f32 "
        "{%0,%1,%2,%3}, {%4,%5,%6,%7}, {%8,%9}, {%0,%1,%2,%3};"
        : "+f"(c[0]), "+f"(c[1]), "+f"(c[2]), "+f"(c[3])
        : "r"(a0), "r"(a1), "r"(a2), "r"(a3), "r"(b0), "r"(b1));
}

__device__ __forceinline__ uint32_t pack2(float a, float b) {
    __half2 h = __floats2half2_rn(a, b);
    return *(uint32_t*)&h;
}
__device__ __forceinline__ uint32_t ex2_h2(uint32_t x) {
    uint32_t r;
    asm("ex2.approx.f16x2 %0, %1;" : "=r"(r) : "r"(x));
    return r;
}

// ===========================================================================
// Fused prep (pure streaming, coalesced)
// ===========================================================================
__global__ void __launch_bounds__(256) prep(
    const float* __restrict__ x,
    const float* __restrict__ Wq, const float* __restrict__ Wk,
    const float* __restrict__ Wv, const float* __restrict__ Wo,
    const float* __restrict__ bq, const float* __restrict__ bk,
    const float* __restrict__ bv,
    __half* __restrict__ x16, __half* __restrict__ wqkv,
    __half* __restrict__ wo16, float* __restrict__ bias)
{
    const int blk = blockIdx.x;
    const int tid = threadIdx.x;
    const float qs = 0.125f * LOG2E;   // 1/sqrt(dh) * log2(e), folded into Wq/bq

    if (blk < 1024) {
#pragma unroll
        for (int p = 0; p < 4; p++) {
            const int j = blk * 1024 + p * 256 + tid;
            float4 v = *(const float4*)(x + (size_t)j * 4);
            *(__half2*)(x16 + (size_t)j * 4)     = __floats2half2_rn(v.x, v.y);
            *(__half2*)(x16 + (size_t)j * 4 + 2) = __floats2half2_rn(v.z, v.w);
        }
        return;
    }
    if (blk < 1792) {
        const int i = blk - 1024;
        const int which = i >> 8;
        const int bi = i & 255;
        const float* W = (which == 0) ? Wq : (which == 1) ? Wk : Wv;
        const float scale = (which == 0) ? qs : 1.0f;
#pragma unroll
        for (int p = 0; p < 4; p++) {
            const int e = bi * 4096 + (p * 256 + tid) * 4;
            const int k = e >> 10, n = e & 1023;
            float4 v = *(const float4*)(W + e);
            __half* dst = wqkv + (size_t)k * 3072 + which * 1024 + n;
            *(__half2*)(dst)     = __floats2half2_rn(v.x * scale, v.y * scale);
            *(__half2*)(dst + 2) = __floats2half2_rn(v.z * scale, v.w * scale);
        }
        return;
    }
    if (blk < 2048) {
        const int bi = blk - 1792;
#pragma unroll
        for (int p = 0; p < 4; p++) {
            const int e = bi * 4096 + (p * 256 + tid) * 4;
            float4 v = *(const float4*)(Wo + e);
            *(__half2*)(wo16 + e)     = __floats2half2_rn(v.x, v.y);
            *(__half2*)(wo16 + e + 2) = __floats2half2_rn(v.z, v.w);
        }
        return;
    }
#pragma unroll
    for (int j = 0; j < 12; j++) {
        const int i = j * 256 + tid;
        float v;
        if (i < 1024)       v = bq[i] * qs;
        else if (i < 2048)  v = bk[i - 1024];
        else                v = bv[i - 2048];
        bias[i] = v;
    }
}

// ===========================================================================
// FP16 mma GEMM (champion): 512 thr, block 256x128, 16 warps (8m x 2n),
// warp tile 32x64, BK=64, 3-stage cp.async. B via ldmatrix.trans from
// W[K,N] (no pre-transpose).
//   mode 0: QKV merged (N=3072, wstride=3072): out -> 3 x [B,H,S,dh] fp16.
//   mode 1: out fp32 row-major [M,1024], wstride=1024.
// ===========================================================================
#define ROWB   144
#define ROWB_B 272
#define GA_TILEB (256 * ROWB)           // 36864
#define GB_TILEB (64 * ROWB_B)          // 17408
#define G_STAGE  (GA_TILEB + GB_TILEB)  // 54272
#define G_SMEM   (3 * G_STAGE)          // 162816

__device__ __forceinline__ void g_load_A(
    const __half* __restrict__ G, uint32_t sbase, int tid)
{
#pragma unroll
    for (int i = 0; i < 4; i++) {
        const int idx = tid + (i << 9);
        const int r = idx >> 3, s = idx & 7;
        cp16(sbase + (uint32_t)(r * ROWB + s * 16), G + (size_t)r * DM + s * 8);
    }
}
__device__ __forceinline__ void g_load_Bw(
    const __half* __restrict__ G, int wstride, uint32_t sbase, int tid)
{
#pragma unroll
    for (int i = 0; i < 2; i++) {
        const int idx = tid + (i << 9);
        const int r = idx >> 4, s = idx & 15;
        cp16(sbase + (uint32_t)(r * ROWB_B + s * 16), G + (size_t)r * wstride + s * 8);
    }
}

__global__ void __launch_bounds__(512, 1) gemm_f16(
    const __half* __restrict__ A, const __half* __restrict__ W, int wstride,
    const float* __restrict__ bias, void* __restrict__ Cout, int mode)
{
    extern __shared__ __align__(16) char smraw[];
    const uint32_t smem0 = (uint32_t)__cvta_generic_to_shared(smraw);

    const int tid  = threadIdx.x;
    const int wid  = tid >> 5, lane = tid & 31;
    const int wm   = wid >> 1, wn = wid & 1;
    const int g    = lane >> 2, kq = lane & 3;
    const int lrow = lane & 15;
    const int lcol = (lane >> 4) * 16;

    const int m0 = blockIdx.y * 256;
    const int n0 = blockIdx.x * 128;

    const __half* Ag = A + (size_t)m0 * DM;
    const __half* Wg = W + n0;

    float c[2][8][4];
#pragma unroll
    for (int mt = 0; mt < 2; mt++)
#pragma unroll
        for (int nt = 0; nt < 8; nt++)
#pragma unroll
            for (int i = 0; i < 4; i++) c[mt][nt][i] = 0.f;

    g_load_A(Ag, smem0, tid);
    g_load_Bw(Wg, wstride, smem0 + GA_TILEB, tid);
    CP_COMMIT();
    g_load_A(Ag + 64, smem0 + G_STAGE, tid);
    g_load_Bw(Wg + (size_t)64 * wstride, wstride, smem0 + G_STAGE + GA_TILEB, tid);
    CP_COMMIT();

    const int NCH = DM / 64;            // 16
    for (int kc = 0; kc < NCH; kc++) {
        if (kc < NCH - 1) { CP_WAIT(1); } else { CP_WAIT(0); }
        __syncthreads();

        if (kc + 2 < NCH) {
            const uint32_t sb = smem0 + (uint32_t)(((kc + 2) % 3) * G_STAGE);
            g_load_A(Ag + (kc + 2) * 64, sb, tid);
            g_load_Bw(Wg + (size_t)(kc + 2) * 64 * wstride, wstride, sb + GA_TILEB, tid);
            CP_COMMIT();
        }

        const uint32_t sA = smem0 + (uint32_t)((kc % 3) * G_STAGE);
        const uint32_t sB = sA + GA_TILEB;
        const uint32_t aBase = sA + (uint32_t)((wm * 32 + lrow) * ROWB) + lcol;
        const uint32_t bBase = sB + (uint32_t)(lrow * ROWB_B) + (uint32_t)(wn * 128) + lcol;

#pragma unroll
        for (int ks = 0; ks < 4; ks++) {
            uint32_t af[2][4], bf[4][4];
#pragma unroll
            for (int mt = 0; mt < 2; mt++)
                ldm_x4(af[mt], aBase + (uint32_t)(mt * 16 * ROWB) + ks * 32);
#pragma unroll
            for (int np = 0; np < 4; np++)
                ldm_x4t(bf[np], bBase + (uint32_t)(ks * 16 * ROWB_B) + np * 32);
#pragma unroll
            for (int mt = 0; mt < 2; mt++) {
#pragma unroll
                for (int np = 0; np < 4; np++) {
                    mma_f16(c[mt][2*np],   af[mt][0], af[mt][1], af[mt][2], af[mt][3],
                            bf[np][0], bf[np][1]);
                    mma_f16(c[mt][2*np+1], af[mt][0], af[mt][1], af[mt][2], af[mt][3],
                            bf[np][2], bf[np][3]);
                }
            }
        }
    }

#pragma unroll
    for (int mt = 0; mt < 2; mt++) {
        const int r1 = m0 + wm * 32 + mt * 16 + g;
        const int r2 = r1 + 8;
        const int b1 = r1 >> 11, s1 = r1 & 2047;
        const int b2 = r2 >> 11, s2 = r2 & 2047;
#pragma unroll
        for (int nt = 0; nt < 8; nt++) {
            const int n = n0 + wn * 64 + nt * 8 + 2 * kq;
            const float bx = bias[n], by = bias[n + 1];
            const float v10 = c[mt][nt][0] + bx, v11 = c[mt][nt][1] + by;
            const float v20 = c[mt][nt][2] + bx, v21 = c[mt][nt][3] + by;
            if (mode == 0) {
                __half* C = (__half*)Cout;
                const int which = n >> 10;
                const int nn = n & 1023;
                const int h = nn >> 6, d = nn & 63;
                const size_t base = (size_t)which * QKV_OFF;
                *(__half2*)(C + base + (((size_t)(b1 * NH + h)) * SEQ + s1) * DH + d) =
                    __floats2half2_rn(v10, v11);
                *(__half2*)(C + base + (((size_t)(b2 * NH + h)) * SEQ + s2) * DH + d) =
                    __floats2half2_rn(v20, v21);
            } else {
                float* C = (float*)Cout;
                *(float2*)(C + (size_t)r1 * DM + n) = make_float2(v10, v11);
                *(float2*)(C + (size_t)r2 * DM + n) = make_float2(v20, v21);
            }
        }
    }
}

// ===========================================================================
// Flash attention (champion): q-tile 256, 8 warps/block, m32/warp,
// BK=128, f32-acc mma, log2-domain scores, P = ex2.approx.f16x2,
// row sums via hadd2 tree on fma/alu pipes.
// ===========================================================================
#define FAQ_BYTES  (256 * ROWB)          // 36864
#define FAKV_BYTES (128 * ROWB)          // 18432
#define FA_SMEM (FAQ_BYTES + 4 * FAKV_BYTES)   // 110592

__device__ __forceinline__ void fa_load_q(
    const __half* __restrict__ G, uint32_t sbase, int tid)
{
#pragma unroll
    for (int i = 0; i < 8; i++) {
        const int idx = tid + (i << 8);
        const int r = idx >> 3, s = idx & 7;
        cp16(sbase + (uint32_t)(r * ROWB + s * 16), G + (size_t)r * DH + s * 8);
    }
}
__device__ __forceinline__ void fa_load_kv(
    const __half* __restrict__ G, uint32_t sbase, int tid)
{
#pragma unroll
    for (int i = 0; i < 4; i++) {
        const int idx = tid + (i << 8);
        const int r = idx >> 3, s = idx & 7;
        cp16(sbase + (uint32_t)(r * ROWB + s * 16), G + (size_t)r * DH + s * 8);
    }
}

__global__ void __launch_bounds__(256) fa_mma(
    const __half* __restrict__ Q, const __half* __restrict__ K,
    const __half* __restrict__ V, __half* __restrict__ Out)
{
    extern __shared__ __align__(16) char smraw[];
    const uint32_t smem0 = (uint32_t)__cvta_generic_to_shared(smraw);
    const uint32_t smQ  = smem0;
    const uint32_t smK0 = smem0 + FAQ_BYTES;
    const uint32_t smK1 = smK0 + FAKV_BYTES;
    const uint32_t smV0 = smK1 + FAKV_BYTES;
    const uint32_t smV1 = smV0 + FAKV_BYTES;

    const int tid = threadIdx.x;
    const int wid = tid >> 5, lane = tid & 31;
    const int g = lane >> 2, kq = lane & 3;
    const int lrow = lane & 15;
    const int lcol = (lane >> 4) * 16;

    const int q0 = blockIdx.x * 256;
    const int bh = blockIdx.y;
    const int b = bh >> 4, h = bh & 15;

    const __half* Qg = Q + (size_t)bh * SEQ * DH + (size_t)q0 * DH;
    const __half* Kg = K + (size_t)bh * SEQ * DH;
    const __half* Vg = V + (size_t)bh * SEQ * DH;

    fa_load_q(Qg, smQ, tid);
    CP_COMMIT();
    fa_load_kv(Kg, smK0, tid);
    fa_load_kv(Vg, smV0, tid);
    CP_COMMIT();

    float mx[2][2], li[2][2];
    float co[2][8][4];
#pragma unroll
    for (int mh = 0; mh < 2; mh++) {
        mx[mh][0] = mx[mh][1] = -INFINITY;
        li[mh][0] = li[mh][1] = 0.f;
#pragma unroll
        for (int nt = 0; nt < 8; nt++)
#pragma unroll
            for (int i = 0; i < 4; i++) co[mh][nt][i] = 0.f;
    }

    const uint32_t qBase = smQ + (uint32_t)((wid * 32 + lrow) * ROWB) + lcol;

    for (int t = 0; t < SEQ / 128; t++) {
        __syncthreads();
        if (t + 1 < SEQ / 128) {
            const uint32_t sKn = ((t + 1) & 1) ? smK1 : smK0;
            const uint32_t sVn = ((t + 1) & 1) ? smV1 : smV0;
            fa_load_kv(Kg + (size_t)(t + 1) * 128 * DH, sKn, tid);
            fa_load_kv(Vg + (size_t)(t + 1) * 128 * DH, sVn, tid);
            CP_COMMIT();
            CP_WAIT(1);
        } else {
            CP_WAIT(0);
        }
        __syncthreads();

        const uint32_t sK = (t & 1) ? smK1 : smK0;
        const uint32_t sV = (t & 1) ? smV1 : smV0;
        const uint32_t kBase = sK + (uint32_t)(lrow * ROWB) + lcol;
        const uint32_t vBase = sV + (uint32_t)(lrow * ROWB) + lcol;

        // ---- scores (log2 domain), f32 acc: S[32 x 128] per warp ----
        float cs[2][16][4];
#pragma unroll
        for (int mh = 0; mh < 2; mh++)
#pragma unroll
            for (int nt = 0; nt < 16; nt++)
#pragma unroll
                for (int i = 0; i < 4; i++) cs[mh][nt][i] = 0.f;

#pragma unroll
        for (int ks = 0; ks < 4; ks++) {
            uint32_t a[2][4];
            ldm_x4(a[0], qBase + ks * 32);
            ldm_x4(a[1], qBase + (uint32_t)(16 * ROWB) + ks * 32);
#pragma unroll
            for (int np = 0; np < 8; np++) {
                uint32_t bb[4];
                ldm_x4(bb, kBase + (uint32_t)(np * 16 * ROWB) + ks * 32);
#pragma unroll
                for (int mh = 0; mh < 2; mh++) {
                    mma_f16(cs[mh][2*np],   a[mh][0], a[mh][1], a[mh][2], a[mh][3],
                            bb[0], bb[2]);
                    mma_f16(cs[mh][2*np+1], a[mh][0], a[mh][1], a[mh][2], a[mh][3],
                            bb[1], bb[3]);
                }
            }
        }

        // ---- online softmax: f32 max + P = 2^(s-m) via ex2.approx.f16x2 ----
        uint32_t p[2][16][2];
        float corr[2][2];
#pragma unroll
        for (int mh = 0; mh < 2; mh++) {
            float tm0 = -INFINITY, tm1 = -INFINITY;
#pragma unroll
            for (int nt = 0; nt < 16; nt++) {
                tm0 = fmaxf(tm0, fmaxf(cs[mh][nt][0], cs[mh][nt][1]));
                tm1 = fmaxf(tm1, fmaxf(cs[mh][nt][2], cs[mh][nt][3]));
            }
            tm0 = fmaxf(tm0, __shfl_xor_sync(0xffffffffu, tm0, 1));
            tm0 = fmaxf(tm0, __shfl_xor_sync(0xffffffffu, tm0, 2));
            tm1 = fmaxf(tm1, __shfl_xor_sync(0xffffffffu, tm1, 1));
            tm1 = fmaxf(tm1, __shfl_xor_sync(0xffffffffu, tm1, 2));

            const float mn0 = fmaxf(mx[mh][0], tm0), mn1 = fmaxf(mx[mh][1], tm1);
            corr[mh][0] = exp2f(mx[mh][0] - mn0);
            corr[mh][1] = exp2f(mx[mh][1] - mn1);
            mx[mh][0] = mn0; mx[mh][1] = mn1;

#pragma unroll
            for (int nt = 0; nt < 16; nt++) {
                p[mh][nt][0] = ex2_h2(pack2(cs[mh][nt][0] - mn0, cs[mh][nt][1] - mn0));
                p[mh][nt][1] = ex2_h2(pack2(cs[mh][nt][2] - mn1, cs[mh][nt][3] - mn1));
            }

            float ts[2];
#pragma unroll
            for (int hf = 0; hf < 2; hf++) {
                __half2 l1[8];
#pragma unroll
                for (int i = 0; i < 8; i++)
                    l1[i] = __hadd2(*(__half2*)&p[mh][2*i][hf],
                                    *(__half2*)&p[mh][2*i+1][hf]);
                __half2 l2[4];
#pragma unroll
                for (int i = 0; i < 4; i++)
                    l2[i] = __hadd2(l1[2*i], l1[2*i+1]);
                float s = 0.f;
#pragma unroll
                for (int i = 0; i < 4; i++) {
                    const float2 f = __half22float2(l2[i]);
                    s += f.x + f.y;
                }
                s += __shfl_xor_sync(0xffffffffu, s, 1);
                s += __shfl_xor_sync(0xffffffffu, s, 2);
                ts[hf] = s;
            }
            li[mh][0] = li[mh][0] * corr[mh][0] + ts[0];
            li[mh][1] = li[mh][1] * corr[mh][1] + ts[1];

#pragma unroll
            for (int nt = 0; nt < 8; nt++) {
                co[mh][nt][0] *= corr[mh][0]; co[mh][nt][1] *= corr[mh][0];
                co[mh][nt][2] *= corr[mh][1]; co[mh][nt][3] *= corr[mh][1];
            }
        }

        // ---- PV (f32 acc) ----
#pragma unroll
        for (int j = 0; j < 8; j++) {
            uint32_t bb[4][4];
#pragma unroll
            for (int np = 0; np < 4; np++)
                ldm_x4t(bb[np], vBase + (uint32_t)(j * 16 * ROWB) + np * 32);
#pragma unroll
            for (int mh = 0; mh < 2; mh++) {
                const uint32_t a0 = p[mh][2*j][0];
                const uint32_t a1 = p[mh][2*j][1];
                const uint32_t a2 = p[mh][2*j+1][0];
                const uint32_t a3 = p[mh][2*j+1][1];
#pragma unroll
                for (int np = 0; np < 4; np++) {
                    mma_f16(co[mh][2*np],   a0, a1, a2, a3, bb[np][0], bb[np][1]);
                    mma_f16(co[mh][2*np+1], a0, a1, a2, a3, bb[np][2], bb[np][3]);
                }
            }
        }
    }

    // ---- epilogue: normalize, write fp16 [B, S, H*dh] ----
#pragma unroll
    for (int mh = 0; mh < 2; mh++) {
        const float inv0 = 1.f / li[mh][0], inv1 = 1.f / li[mh][1];
        const int qrow = wid * 32 + mh * 16 + g;
        __half* Og = Out + ((size_t)b * SEQ + (q0 + qrow)) * DM + h * DH;
#pragma unroll
        for (int nt = 0; nt < 8; nt++) {
            *(__half2*)(Og + 8 * nt + 2 * kq) =
                __floats2half2_rn(co[mh][nt][0] * inv0, co[mh][nt][1] * inv0);
            *(__half2*)(Og + (size_t)8 * DM + 8 * nt + 2 * kq) =
                __floats2half2_rn(co[mh][nt][2] * inv1, co[mh][nt][3] * inv1);
        }
    }
}

// ---------------------------------------------------------------------------
// Launch
// ---------------------------------------------------------------------------
extern "C" void kernel_launch(void* const* d_in, const int* in_sizes, int n_in,
                              void* d_out, int out_size)
{
    const float* x  = (const float*)d_in[0];
    // d_in[1] = pH : constant along softmax axis -> provably no effect
    const float* Wq = (const float*)d_in[2];
    const float* bq = (const float*)d_in[3];
    const float* Wk = (const float*)d_in[4];
    const float* bk = (const float*)d_in[5];
    const float* Wv = (const float*)d_in[6];
    const float* bv = (const float*)d_in[7];
    const float* Wo = (const float*)d_in[8];
    const float* bo = (const float*)d_in[9];
    float* out = (float*)d_out;

    __half *x16, *qkv, *att, *wqkv, *wo16;
    float *bias;
    cudaGetSymbolAddress((void**)&x16,  g_X16);
    cudaGetSymbolAddress((void**)&qkv,  g_QKV);
    cudaGetSymbolAddress((void**)&att,  g_ATT);
    cudaGetSymbolAddress((void**)&wqkv, g_WQKV);
    cudaGetSymbolAddress((void**)&wo16, g_WO);
    cudaGetSymbolAddress((void**)&bias, g_BIAS);

    cudaFuncSetAttribute(gemm_f16, cudaFuncAttributeMaxDynamicSharedMemorySize, G_SMEM);
    cudaFuncSetAttribute(fa_mma,   cudaFuncAttributeMaxDynamicSharedMemorySize, FA_SMEM);

    // Fused streaming prep: f2h(x) + W pack/convert (no transpose) + bias
    prep<<<2049, 256>>>(x, Wq, Wk, Wv, Wo, bq, bk, bv, x16, wqkv, wo16, bias);

    // Merged QKV projection: N = 3072, W in [K, 3N] layout
    dim3 gq(3 * DM / 128, MROWS / 256);   // (24, 16)
    gemm_f16<<<gq, 512, G_SMEM>>>(x16, wqkv, 3072, bias, qkv, 0);

    // Attention, q-tile 256 (champion config)
    dim3 ga(SEQ / 256, BATCH * NH);       // (8, 32) = 256 CTAs
    fa_mma<<<ga, 256, FA_SMEM>>>(qkv, qkv + QKV_OFF, qkv + 2 * QKV_OFF, att);

    // Output projection (fp32 out)
    dim3 go(DM / 128, MROWS / 256);       // (8, 16)
    gemm_f16<<<go, 512, G_SMEM>>>(att, wo16, 1024, bo, out, 1);
}